// round 14
// baseline (speedup 1.0000x reference)
#include <cuda_runtime.h>
#include <cuda_bf16.h>
#include <cuda_fp16.h>
#include <cstdint>
#include <math.h>

// ============================================================
// R14: R13 (persistent tickets, 2 CTAs/SM, 2-stage cp.async ring,
// QK bf16 3-term, PV single fp16, log2 softmax, per-lane l) plus:
//  1. anti-phase stagger: the second co-resident CTA (bid>=152)
//     delays ~half an iteration once at start, so the two CTAs'
//     softmax phases interleave and the tensor pipe stays fed.
//  2. skip-rescale: if no row max changed in the warp (a==1
//     exactly), skip the O rescale (bit-exact shortcut).
// ============================================================

constexpr int kS = 2048, kD = 128, kBQ = 64, kBK = 64;
constexpr int kThreads = 128;
constexpr int kIters = kS / kBK;            // 32
constexpr int kQTiles = kS / kBQ;           // 32
constexpr int kTiles  = kQTiles * 32;       // 1024 work units
constexpr int kPersistentCTAs = 304;        // 2 per SM x 152 SMs

constexpr int kKVStrideB = 272;
constexpr int kKVTileB   = 64 * kKVStrideB; // 17408
constexpr int kBlobB     = 3 * kKVTileB;    // khi,klo,vhi = 52224
constexpr int kKVOps     = kBlobB / 16;     // 3264
constexpr int kSmemBytes = 2 * kBlobB + 16; // 104464

__device__ __align__(16) unsigned char g_kv[32u * 32u * (unsigned)kBlobB];
__device__ int g_ticket;

__device__ __forceinline__ uint32_t smem_u32(const void* p) {
    uint32_t a;
    asm("{ .reg .u64 t; cvta.to.shared.u64 t, %1; cvt.u32.u64 %0, t; }" : "=r"(a) : "l"(p));
    return a;
}
__device__ __forceinline__ void cp16(uint32_t dst, const void* src) {
    asm volatile("cp.async.cg.shared.global [%0], [%1], 16;" :: "r"(dst), "l"(src));
}
__device__ __forceinline__ void cp_commit() { asm volatile("cp.async.commit_group;" ::: "memory"); }
__device__ __forceinline__ void cp_wait0()  { asm volatile("cp.async.wait_group 0;" ::: "memory"); }

__device__ __forceinline__ void ldsm_x4(uint32_t& r0, uint32_t& r1, uint32_t& r2, uint32_t& r3,
                                        uint32_t addr) {
    asm volatile("ldmatrix.sync.aligned.m8n8.x4.shared.b16 {%0,%1,%2,%3}, [%4];"
        : "=r"(r0), "=r"(r1), "=r"(r2), "=r"(r3) : "r"(addr));
}
__device__ __forceinline__ void ldsm_x4_t(uint32_t& r0, uint32_t& r1, uint32_t& r2, uint32_t& r3,
                                          uint32_t addr) {
    asm volatile("ldmatrix.sync.aligned.m8n8.x4.trans.shared.b16 {%0,%1,%2,%3}, [%4];"
        : "=r"(r0), "=r"(r1), "=r"(r2), "=r"(r3) : "r"(addr));
}
__device__ __forceinline__ void mma_bf16(float* d, const uint32_t* a, uint32_t b0, uint32_t b1) {
    asm volatile("mma.sync.aligned.m16n8k16.row.col.f32.bf16.bf16.f32 "
        "{%0,%1,%2,%3}, {%4,%5,%6,%7}, {%8,%9}, {%0,%1,%2,%3};"
        : "+f"(d[0]), "+f"(d[1]), "+f"(d[2]), "+f"(d[3])
        : "r"(a[0]), "r"(a[1]), "r"(a[2]), "r"(a[3]), "r"(b0), "r"(b1));
}
__device__ __forceinline__ void mma_f16(float* d, const uint32_t* a, uint32_t b0, uint32_t b1) {
    asm volatile("mma.sync.aligned.m16n8k16.row.col.f32.f16.f16.f32 "
        "{%0,%1,%2,%3}, {%4,%5,%6,%7}, {%8,%9}, {%0,%1,%2,%3};"
        : "+f"(d[0]), "+f"(d[1]), "+f"(d[2]), "+f"(d[3])
        : "r"(a[0]), "r"(a[1]), "r"(a[2]), "r"(a[3]), "r"(b0), "r"(b1));
}
__device__ __forceinline__ float ex2(float x) {
    float r;
    asm("ex2.approx.ftz.f32 %0, %1;" : "=f"(r) : "f"(x));
    return r;
}
__device__ __forceinline__ uint32_t packbf(float a, float b) {
    __nv_bfloat162 t = __floats2bfloat162_rn(a, b);
    return *reinterpret_cast<uint32_t*>(&t);
}
__device__ __forceinline__ uint32_t packh(float a, float b) {
    __half2 t = __floats2half2_rn(a, b);
    return *reinterpret_cast<uint32_t*>(&t);
}
__device__ __forceinline__ void split2(float a, float b, uint32_t& hi, uint32_t& lo) {
    __nv_bfloat16 ah = __float2bfloat16(a), bh = __float2bfloat16(b);
    __nv_bfloat162 h; h.x = ah; h.y = bh;
    hi = *reinterpret_cast<uint32_t*>(&h);
    lo = packbf(a - __bfloat162float(ah), b - __bfloat162float(bh));
}
__device__ __forceinline__ float decode_scalar(const void* p) {
    const int w = *reinterpret_cast<const int*>(p);
    if (w > -(1 << 23) && w < (1 << 23)) return (float)w;
    return __int_as_float(w);
}

// ---------------- ticket reset ----------------
__global__ void reset_ticket_kernel() { g_ticket = 0; }

// ---------------- precompute: K -> bf16 hi/lo, V -> fp16 ----------------
__global__ __launch_bounds__(256, 4)
void convert_kv_kernel(const float* __restrict__ k, const float* __restrict__ v) {
    const int kt = (int)blockIdx.x, bh = (int)blockIdx.y, tid = (int)threadIdx.x;
    unsigned char* blob = g_kv + (size_t)(bh * 32 + kt) * kBlobB;
    const float* kgt = k + ((size_t)bh * kS + (size_t)kt * kBK) * kD;
    const float* vgt = v + ((size_t)bh * kS + (size_t)kt * kBK) * kD;
    #pragma unroll
    for (int it = 0; it < 8; ++it) {
        const int idx = it * 256 + tid;
        const int r = idx >> 5, c = (idx & 31) << 2;
        const int so = r * kKVStrideB + c * 2;
        {
            const float4 x = reinterpret_cast<const float4*>(kgt)[idx];
            uint32_t h0, l0, h1, l1;
            split2(x.x, x.y, h0, l0);
            split2(x.z, x.w, h1, l1);
            *reinterpret_cast<uint2*>(blob + so)            = make_uint2(h0, h1);
            *reinterpret_cast<uint2*>(blob + kKVTileB + so) = make_uint2(l0, l1);
        }
        {
            const float4 x = reinterpret_cast<const float4*>(vgt)[idx];
            *reinterpret_cast<uint2*>(blob + 2 * kKVTileB + so) =
                make_uint2(packh(x.x, x.y), packh(x.z, x.w));
        }
    }
}

// ---------------- main persistent kernel ----------------
__global__ __launch_bounds__(kThreads, 2)
void flash_mma_kernel(const float* __restrict__ q,
                      const float* __restrict__ sf,
                      const void*  __restrict__ dropout_p,
                      float* __restrict__ out) {
    extern __shared__ char smem[];
    const uint32_t sb = smem_u32(smem);
    int* ticket_sm = reinterpret_cast<int*>(smem + 2 * kBlobB);
    const int tid  = (int)threadIdx.x;
    const int wid  = tid >> 5;
    const int lane = tid & 31;
    const int g    = lane >> 2;
    const int t    = lane & 3;
    const int w8   = lane & 7;
    const int b3   = (lane >> 3) & 1;
    const int b4   = (lane >> 4) & 1;
    constexpr float kLog2e = 1.4426950408889634f;
    const float dp = decode_scalar(dropout_p);

    // ---- anti-phase stagger: second co-resident CTA delays ~half an
    // iteration so the two CTAs' softmax phases interleave on each SMSP.
    if ((int)blockIdx.x >= 152) {
        const unsigned long long t0 = clock64();
        while (clock64() - t0 < 4000ull) {}
    }

    while (true) {
        if (tid == 0) *ticket_sm = atomicAdd(&g_ticket, 1);
        __syncthreads();
        const int tile = *ticket_sm;
        __syncthreads();
        if (tile >= kTiles) break;
        const int qt = tile & (kQTiles - 1);
        const int bh = tile >> 5;

        auto issue_tile = [&](int kt, int stage) {
            const unsigned char* src = g_kv + (size_t)(bh * 32 + kt) * kBlobB;
            const uint32_t dkv = sb + (uint32_t)stage * kBlobB;
            #pragma unroll
            for (int i = 0; i < 26; ++i) {
                const int op = i * kThreads + tid;
                if (op < kKVOps) cp16(dkv + op * 16, src + (size_t)op * 16);
            }
            cp_commit();
        };
        issue_tile(0, 0);

        // ---- Q fragments (bf16 hi/lo) ----
        const float* qg = q + ((size_t)bh * kS + (size_t)qt * kBQ) * kD;
        uint32_t qhi[8][4], qlo[8][4];
        {
            const float* rq0 = qg + (size_t)(wid * 16 + g) * kD;
            const float* rq8 = rq0 + 8 * kD;
            #pragma unroll
            for (int ks = 0; ks < 8; ++ks) {
                const int c = ks * 16 + 2 * t;
                const float2 f0 = *reinterpret_cast<const float2*>(rq0 + c);
                const float2 f1 = *reinterpret_cast<const float2*>(rq8 + c);
                const float2 f2 = *reinterpret_cast<const float2*>(rq0 + c + 8);
                const float2 f3 = *reinterpret_cast<const float2*>(rq8 + c + 8);
                split2(f0.x, f0.y, qhi[ks][0], qlo[ks][0]);
                split2(f1.x, f1.y, qhi[ks][1], qlo[ks][1]);
                split2(f2.x, f2.y, qhi[ks][2], qlo[ks][2]);
                split2(f3.x, f3.y, qhi[ks][3], qlo[ks][3]);
            }
        }

        float oacc[16][4];
        #pragma unroll
        for (int n = 0; n < 16; ++n)
            #pragma unroll
            for (int c = 0; c < 4; ++c) oacc[n][c] = 0.f;
        float m0 = -INFINITY, m1 = -INFINITY, l0 = 0.f, l1 = 0.f;

        const float* scr0 = sf + ((size_t)(qt * kBQ) + (size_t)(wid * 16 + g)) * kS + 2 * t;
        const float* scr1 = scr0 + (size_t)8 * kS;

        for (int kt = 0; kt < kIters; ++kt) {
            cp_wait0();
            __syncthreads();
            if (kt + 1 < kIters) issue_tile(kt + 1, (kt + 1) & 1);

            const int st = kt & 1;
            const uint32_t KHI = sb + (uint32_t)st * kBlobB;
            const uint32_t KLO = KHI + kKVTileB;
            const uint32_t VHI = KHI + 2 * kKVTileB;

            const float* scg0 = scr0 + (size_t)kt * kBK;
            const float* scg1 = scr1 + (size_t)kt * kBK;
            float2 sc0[8], sc1[8];
            #pragma unroll
            for (int n = 0; n < 8; ++n) {
                sc0[n] = *reinterpret_cast<const float2*>(scg0 + n * 8);
                sc1[n] = *reinterpret_cast<const float2*>(scg1 + n * 8);
                sc0[n].x *= kLog2e; sc0[n].y *= kLog2e;
                sc1[n].x *= kLog2e; sc1[n].y *= kLog2e;
            }

            // ---- S = Q K^T (bf16 3-term) ----
            float sacc[8][4];
            #pragma unroll
            for (int n = 0; n < 8; ++n)
                #pragma unroll
                for (int c = 0; c < 4; ++c) sacc[n][c] = 0.f;

            #pragma unroll
            for (int ks = 0; ks < 8; ++ks) {
                uint32_t bhi[8][2], blo[8][2];
                #pragma unroll
                for (int p = 0; p < 4; ++p) {
                    const uint32_t off = (uint32_t)((p * 16 + b4 * 8 + w8) * kKVStrideB
                                                    + (ks * 16 + b3 * 8) * 2);
                    ldsm_x4(bhi[2*p][0], bhi[2*p][1], bhi[2*p+1][0], bhi[2*p+1][1], KHI + off);
                    ldsm_x4(blo[2*p][0], blo[2*p][1], blo[2*p+1][0], blo[2*p+1][1], KLO + off);
                }
                #pragma unroll
                for (int n = 0; n < 8; ++n) {
                    mma_bf16(sacc[n], qhi[ks], bhi[n][0], bhi[n][1]);
                    mma_bf16(sacc[n], qhi[ks], blo[n][0], blo[n][1]);
                    mma_bf16(sacc[n], qlo[ks], bhi[n][0], bhi[n][1]);
                }
            }

            // ---- scale (log2 domain) + online softmax ----
            float mx0 = -INFINITY, mx1 = -INFINITY;
            #pragma unroll
            for (int n = 0; n < 8; ++n) {
                sacc[n][0] *= sc0[n].x; sacc[n][1] *= sc0[n].y;
                sacc[n][2] *= sc1[n].x; sacc[n][3] *= sc1[n].y;
                mx0 = fmaxf(mx0, fmaxf(sacc[n][0], sacc[n][1]));
                mx1 = fmaxf(mx1, fmaxf(sacc[n][2], sacc[n][3]));
            }
            #pragma unroll
            for (int off = 1; off <= 2; off <<= 1) {
                mx0 = fmaxf(mx0, __shfl_xor_sync(0xffffffffu, mx0, off));
                mx1 = fmaxf(mx1, __shfl_xor_sync(0xffffffffu, mx1, off));
            }
            const float m0n = fmaxf(m0, mx0), m1n = fmaxf(m1, mx1);
            const bool unchanged = (m0n == m0) && (m1n == m1);

            float sum0 = 0.f, sum1 = 0.f;
            #pragma unroll
            for (int n = 0; n < 8; ++n) {
                sacc[n][0] = ex2(sacc[n][0] - m0n);
                sacc[n][1] = ex2(sacc[n][1] - m0n);
                sacc[n][2] = ex2(sacc[n][2] - m1n);
                sacc[n][3] = ex2(sacc[n][3] - m1n);
                sum0 += sacc[n][0] + sacc[n][1];
                sum1 += sacc[n][2] + sacc[n][3];
            }

            if (__all_sync(0xffffffffu, unchanged)) {
                // a0 = a1 = 1 exactly for the whole warp: skip rescale
                l0 += sum0;
                l1 += sum1;
            } else {
                const float a0 = ex2(m0 - m0n), a1 = ex2(m1 - m1n);
                m0 = m0n; m1 = m1n;
                l0 = l0 * a0 + sum0;
                l1 = l1 * a1 + sum1;
                #pragma unroll
                for (int n = 0; n < 16; ++n) {
                    oacc[n][0] *= a0; oacc[n][1] *= a0;
                    oacc[n][2] *= a1; oacc[n][3] *= a1;
                }
            }

            // ---- repack P (fp16) -> A-frags ----
            uint32_t phi[4][4];
            #pragma unroll
            for (int j = 0; j < 4; ++j) {
                phi[j][0] = packh(sacc[2*j][0],   sacc[2*j][1]);
                phi[j][1] = packh(sacc[2*j][2],   sacc[2*j][3]);
                phi[j][2] = packh(sacc[2*j+1][0], sacc[2*j+1][1]);
                phi[j][3] = packh(sacc[2*j+1][2], sacc[2*j+1][3]);
            }

            // ---- O += P V (single fp16 term) ----
            #pragma unroll
            for (int j = 0; j < 4; ++j) {
                #pragma unroll
                for (int pp = 0; pp < 8; ++pp) {
                    const uint32_t off = (uint32_t)((j * 16 + b3 * 8 + w8) * kKVStrideB
                                                    + (pp * 16 + b4 * 8) * 2);
                    uint32_t vh0, vh1, vh2, vh3;
                    ldsm_x4_t(vh0, vh1, vh2, vh3, VHI + off);
                    mma_f16(oacc[2*pp],   phi[j], vh0, vh1);
                    mma_f16(oacc[2*pp+1], phi[j], vh2, vh3);
                }
            }
        }

        // ---- per-tile epilogue ----
        float L0 = l0, L1 = l1;
        #pragma unroll
        for (int off = 1; off <= 2; off <<= 1) {
            L0 += __shfl_xor_sync(0xffffffffu, L0, off);
            L1 += __shfl_xor_sync(0xffffffffu, L1, off);
        }
        const float inv0 = dp / L0, inv1 = dp / L1;
        const size_t row0 = (size_t)bh * kS + (size_t)qt * kBQ + (size_t)(wid * 16 + g);
        float* o0 = out + row0 * kD + 2 * t;
        float* o1 = o0 + (size_t)8 * kD;
        #pragma unroll
        for (int n = 0; n < 16; ++n) {
            *reinterpret_cast<float2*>(o0 + n * 8) = make_float2(oacc[n][0] * inv0, oacc[n][1] * inv0);
            *reinterpret_cast<float2*>(o1 + n * 8) = make_float2(oacc[n][2] * inv1, oacc[n][3] * inv1);
        }
    }
}

extern "C" void kernel_launch(void* const* d_in, const int* in_sizes, int n_in,
                              void* d_out, int out_size) {
    const float* q  = (const float*)d_in[0];
    const float* k  = (const float*)d_in[1];
    const float* v  = (const float*)d_in[2];
    const float* sf = (const float*)d_in[3];
    const void*  dp = d_in[4];
    float* out = (float*)d_out;
    (void)in_sizes; (void)n_in; (void)out_size;

    reset_ticket_kernel<<<1, 1>>>();
    dim3 cgrid(kIters, 32);
    convert_kv_kernel<<<cgrid, 256>>>(k, v);

    cudaFuncSetAttribute(flash_mma_kernel,
                         cudaFuncAttributeMaxDynamicSharedMemorySize, kSmemBytes);
    flash_mma_kernel<<<kPersistentCTAs, kThreads, kSmemBytes>>>(q, sf, dp, out);
}

// round 15
// speedup vs baseline: 1.6187x; 1.6187x over previous
#include <cuda_runtime.h>
#include <cuda_bf16.h>
#include <cuda_fp16.h>
#include <cstdint>
#include <math.h>

// ============================================================
// R15: R13 exact revert (persistent tickets, 2 CTAs/SM, 2-stage
// cp.async ring, QK bf16 3-term, PV single fp16, log2 softmax,
// per-lane l) + tile-seam hiding:
//   - next ticket popped during last k-iter; next tile's stage-0
//     KV copy issued BEFORE the epilogue (stage 0 free after the
//     iter-31 sync) -> first-fill latency overlaps epilogue+Qload
//   - ticket reset folded into convert kernel (one less launch)
// Hot loop body byte-identical to R13.
// ============================================================

constexpr int kS = 2048, kD = 128, kBQ = 64, kBK = 64;
constexpr int kThreads = 128;
constexpr int kIters = kS / kBK;            // 32
constexpr int kQTiles = kS / kBQ;           // 32
constexpr int kTiles  = kQTiles * 32;       // 1024 work units
constexpr int kPersistentCTAs = 304;        // 2 per SM x 152 SMs

constexpr int kKVStrideB = 272;
constexpr int kKVTileB   = 64 * kKVStrideB; // 17408
constexpr int kBlobB     = 3 * kKVTileB;    // khi,klo,vhi = 52224
constexpr int kKVOps     = kBlobB / 16;     // 3264
constexpr int kSmemBytes = 2 * kBlobB + 16; // 104464

__device__ __align__(16) unsigned char g_kv[32u * 32u * (unsigned)kBlobB];
__device__ int g_ticket;

__device__ __forceinline__ uint32_t smem_u32(const void* p) {
    uint32_t a;
    asm("{ .reg .u64 t; cvta.to.shared.u64 t, %1; cvt.u32.u64 %0, t; }" : "=r"(a) : "l"(p));
    return a;
}
__device__ __forceinline__ void cp16(uint32_t dst, const void* src) {
    asm volatile("cp.async.cg.shared.global [%0], [%1], 16;" :: "r"(dst), "l"(src));
}
__device__ __forceinline__ void cp_commit() { asm volatile("cp.async.commit_group;" ::: "memory"); }
__device__ __forceinline__ void cp_wait0()  { asm volatile("cp.async.wait_group 0;" ::: "memory"); }

__device__ __forceinline__ void ldsm_x4(uint32_t& r0, uint32_t& r1, uint32_t& r2, uint32_t& r3,
                                        uint32_t addr) {
    asm volatile("ldmatrix.sync.aligned.m8n8.x4.shared.b16 {%0,%1,%2,%3}, [%4];"
        : "=r"(r0), "=r"(r1), "=r"(r2), "=r"(r3) : "r"(addr));
}
__device__ __forceinline__ void ldsm_x4_t(uint32_t& r0, uint32_t& r1, uint32_t& r2, uint32_t& r3,
                                          uint32_t addr) {
    asm volatile("ldmatrix.sync.aligned.m8n8.x4.trans.shared.b16 {%0,%1,%2,%3}, [%4];"
        : "=r"(r0), "=r"(r1), "=r"(r2), "=r"(r3) : "r"(addr));
}
__device__ __forceinline__ void mma_bf16(float* d, const uint32_t* a, uint32_t b0, uint32_t b1) {
    asm volatile("mma.sync.aligned.m16n8k16.row.col.f32.bf16.bf16.f32 "
        "{%0,%1,%2,%3}, {%4,%5,%6,%7}, {%8,%9}, {%0,%1,%2,%3};"
        : "+f"(d[0]), "+f"(d[1]), "+f"(d[2]), "+f"(d[3])
        : "r"(a[0]), "r"(a[1]), "r"(a[2]), "r"(a[3]), "r"(b0), "r"(b1));
}
__device__ __forceinline__ void mma_f16(float* d, const uint32_t* a, uint32_t b0, uint32_t b1) {
    asm volatile("mma.sync.aligned.m16n8k16.row.col.f32.f16.f16.f32 "
        "{%0,%1,%2,%3}, {%4,%5,%6,%7}, {%8,%9}, {%0,%1,%2,%3};"
        : "+f"(d[0]), "+f"(d[1]), "+f"(d[2]), "+f"(d[3])
        : "r"(a[0]), "r"(a[1]), "r"(a[2]), "r"(a[3]), "r"(b0), "r"(b1));
}
__device__ __forceinline__ float ex2(float x) {
    float r;
    asm("ex2.approx.ftz.f32 %0, %1;" : "=f"(r) : "f"(x));
    return r;
}
__device__ __forceinline__ uint32_t packbf(float a, float b) {
    __nv_bfloat162 t = __floats2bfloat162_rn(a, b);
    return *reinterpret_cast<uint32_t*>(&t);
}
__device__ __forceinline__ uint32_t packh(float a, float b) {
    __half2 t = __floats2half2_rn(a, b);
    return *reinterpret_cast<uint32_t*>(&t);
}
__device__ __forceinline__ void split2(float a, float b, uint32_t& hi, uint32_t& lo) {
    __nv_bfloat16 ah = __float2bfloat16(a), bh = __float2bfloat16(b);
    __nv_bfloat162 h; h.x = ah; h.y = bh;
    hi = *reinterpret_cast<uint32_t*>(&h);
    lo = packbf(a - __bfloat162float(ah), b - __bfloat162float(bh));
}
__device__ __forceinline__ float decode_scalar(const void* p) {
    const int w = *reinterpret_cast<const int*>(p);
    if (w > -(1 << 23) && w < (1 << 23)) return (float)w;
    return __int_as_float(w);
}

// ---------------- precompute: K -> bf16 hi/lo, V -> fp16; resets ticket ----------------
__global__ __launch_bounds__(256, 4)
void convert_kv_kernel(const float* __restrict__ k, const float* __restrict__ v) {
    const int kt = (int)blockIdx.x, bh = (int)blockIdx.y, tid = (int)threadIdx.x;
    if (kt == 0 && bh == 0 && tid == 0) g_ticket = 0;   // main kernel launches after us
    unsigned char* blob = g_kv + (size_t)(bh * 32 + kt) * kBlobB;
    const float* kgt = k + ((size_t)bh * kS + (size_t)kt * kBK) * kD;
    const float* vgt = v + ((size_t)bh * kS + (size_t)kt * kBK) * kD;
    #pragma unroll
    for (int it = 0; it < 8; ++it) {
        const int idx = it * 256 + tid;
        const int r = idx >> 5, c = (idx & 31) << 2;
        const int so = r * kKVStrideB + c * 2;
        {
            const float4 x = reinterpret_cast<const float4*>(kgt)[idx];
            uint32_t h0, l0, h1, l1;
            split2(x.x, x.y, h0, l0);
            split2(x.z, x.w, h1, l1);
            *reinterpret_cast<uint2*>(blob + so)            = make_uint2(h0, h1);
            *reinterpret_cast<uint2*>(blob + kKVTileB + so) = make_uint2(l0, l1);
        }
        {
            const float4 x = reinterpret_cast<const float4*>(vgt)[idx];
            *reinterpret_cast<uint2*>(blob + 2 * kKVTileB + so) =
                make_uint2(packh(x.x, x.y), packh(x.z, x.w));
        }
    }
}

// ---------------- main persistent kernel ----------------
__global__ __launch_bounds__(kThreads, 2)
void flash_mma_kernel(const float* __restrict__ q,
                      const float* __restrict__ sf,
                      const void*  __restrict__ dropout_p,
                      float* __restrict__ out) {
    extern __shared__ char smem[];
    const uint32_t sb = smem_u32(smem);
    int* ticket_sm  = reinterpret_cast<int*>(smem + 2 * kBlobB);
    int* ticket_sm2 = ticket_sm + 1;
    const int tid  = (int)threadIdx.x;
    const int wid  = tid >> 5;
    const int lane = tid & 31;
    const int g    = lane >> 2;
    const int t    = lane & 3;
    const int w8   = lane & 7;
    const int b3   = (lane >> 3) & 1;
    const int b4   = (lane >> 4) & 1;
    constexpr float kLog2e = 1.4426950408889634f;
    const float dp = decode_scalar(dropout_p);

    auto copy_blob = [&](int bh, int kt, int stage) {
        const unsigned char* src = g_kv + (size_t)(bh * 32 + kt) * kBlobB;
        const uint32_t dkv = sb + (uint32_t)stage * kBlobB;
        #pragma unroll
        for (int i = 0; i < 26; ++i) {
            const int op = i * kThreads + tid;
            if (op < kKVOps) cp16(dkv + op * 16, src + (size_t)op * 16);
        }
        cp_commit();
    };

    // ---- initial ticket pop + stage-0 prefetch ----
    if (tid == 0) *ticket_sm = atomicAdd(&g_ticket, 1);
    __syncthreads();
    int tile = *ticket_sm;
    if (tile < kTiles) copy_blob(tile >> 5, 0, 0);

    while (tile < kTiles) {
        const int qt = tile & (kQTiles - 1);
        const int bh = tile >> 5;

        // ---- Q fragments (bf16 hi/lo) ----
        const float* qg = q + ((size_t)bh * kS + (size_t)qt * kBQ) * kD;
        uint32_t qhi[8][4], qlo[8][4];
        {
            const float* rq0 = qg + (size_t)(wid * 16 + g) * kD;
            const float* rq8 = rq0 + 8 * kD;
            #pragma unroll
            for (int ks = 0; ks < 8; ++ks) {
                const int c = ks * 16 + 2 * t;
                const float2 f0 = *reinterpret_cast<const float2*>(rq0 + c);
                const float2 f1 = *reinterpret_cast<const float2*>(rq8 + c);
                const float2 f2 = *reinterpret_cast<const float2*>(rq0 + c + 8);
                const float2 f3 = *reinterpret_cast<const float2*>(rq8 + c + 8);
                split2(f0.x, f0.y, qhi[ks][0], qlo[ks][0]);
                split2(f1.x, f1.y, qhi[ks][1], qlo[ks][1]);
                split2(f2.x, f2.y, qhi[ks][2], qlo[ks][2]);
                split2(f3.x, f3.y, qhi[ks][3], qlo[ks][3]);
            }
        }

        float oacc[16][4];
        #pragma unroll
        for (int n = 0; n < 16; ++n)
            #pragma unroll
            for (int c = 0; c < 4; ++c) oacc[n][c] = 0.f;
        float m0 = -INFINITY, m1 = -INFINITY, l0 = 0.f, l1 = 0.f;

        const float* scr0 = sf + ((size_t)(qt * kBQ) + (size_t)(wid * 16 + g)) * kS + 2 * t;
        const float* scr1 = scr0 + (size_t)8 * kS;

        for (int kt = 0; kt < kIters; ++kt) {
            cp_wait0();
            __syncthreads();
            if (kt + 1 < kIters) copy_blob(bh, kt + 1, (kt + 1) & 1);
            // pop next ticket during the final iteration (hidden behind MMAs)
            if (kt == kIters - 1 && tid == 0) *ticket_sm2 = atomicAdd(&g_ticket, 1);

            const int st = kt & 1;
            const uint32_t KHI = sb + (uint32_t)st * kBlobB;
            const uint32_t KLO = KHI + kKVTileB;
            const uint32_t VHI = KHI + 2 * kKVTileB;

            const float* scg0 = scr0 + (size_t)kt * kBK;
            const float* scg1 = scr1 + (size_t)kt * kBK;
            float2 sc0[8], sc1[8];
            #pragma unroll
            for (int n = 0; n < 8; ++n) {
                sc0[n] = *reinterpret_cast<const float2*>(scg0 + n * 8);
                sc1[n] = *reinterpret_cast<const float2*>(scg1 + n * 8);
                sc0[n].x *= kLog2e; sc0[n].y *= kLog2e;
                sc1[n].x *= kLog2e; sc1[n].y *= kLog2e;
            }

            // ---- S = Q K^T (bf16 3-term) ----
            float sacc[8][4];
            #pragma unroll
            for (int n = 0; n < 8; ++n)
                #pragma unroll
                for (int c = 0; c < 4; ++c) sacc[n][c] = 0.f;

            #pragma unroll
            for (int ks = 0; ks < 8; ++ks) {
                uint32_t bhi[8][2], blo[8][2];
                #pragma unroll
                for (int p = 0; p < 4; ++p) {
                    const uint32_t off = (uint32_t)((p * 16 + b4 * 8 + w8) * kKVStrideB
                                                    + (ks * 16 + b3 * 8) * 2);
                    ldsm_x4(bhi[2*p][0], bhi[2*p][1], bhi[2*p+1][0], bhi[2*p+1][1], KHI + off);
                    ldsm_x4(blo[2*p][0], blo[2*p][1], blo[2*p+1][0], blo[2*p+1][1], KLO + off);
                }
                #pragma unroll
                for (int n = 0; n < 8; ++n) {
                    mma_bf16(sacc[n], qhi[ks], bhi[n][0], bhi[n][1]);
                    mma_bf16(sacc[n], qhi[ks], blo[n][0], blo[n][1]);
                    mma_bf16(sacc[n], qlo[ks], bhi[n][0], bhi[n][1]);
                }
            }

            // ---- scale (log2 domain) + online softmax ----
            float mx0 = -INFINITY, mx1 = -INFINITY;
            #pragma unroll
            for (int n = 0; n < 8; ++n) {
                sacc[n][0] *= sc0[n].x; sacc[n][1] *= sc0[n].y;
                sacc[n][2] *= sc1[n].x; sacc[n][3] *= sc1[n].y;
                mx0 = fmaxf(mx0, fmaxf(sacc[n][0], sacc[n][1]));
                mx1 = fmaxf(mx1, fmaxf(sacc[n][2], sacc[n][3]));
            }
            #pragma unroll
            for (int off = 1; off <= 2; off <<= 1) {
                mx0 = fmaxf(mx0, __shfl_xor_sync(0xffffffffu, mx0, off));
                mx1 = fmaxf(mx1, __shfl_xor_sync(0xffffffffu, mx1, off));
            }
            const float m0n = fmaxf(m0, mx0), m1n = fmaxf(m1, mx1);
            const float a0 = ex2(m0 - m0n), a1 = ex2(m1 - m1n);
            m0 = m0n; m1 = m1n;

            float sum0 = 0.f, sum1 = 0.f;
            #pragma unroll
            for (int n = 0; n < 8; ++n) {
                sacc[n][0] = ex2(sacc[n][0] - m0n);
                sacc[n][1] = ex2(sacc[n][1] - m0n);
                sacc[n][2] = ex2(sacc[n][2] - m1n);
                sacc[n][3] = ex2(sacc[n][3] - m1n);
                sum0 += sacc[n][0] + sacc[n][1];
                sum1 += sacc[n][2] + sacc[n][3];
            }
            l0 = l0 * a0 + sum0;
            l1 = l1 * a1 + sum1;

            #pragma unroll
            for (int n = 0; n < 16; ++n) {
                oacc[n][0] *= a0; oacc[n][1] *= a0;
                oacc[n][2] *= a1; oacc[n][3] *= a1;
            }

            // ---- repack P (fp16) -> A-frags ----
            uint32_t phi[4][4];
            #pragma unroll
            for (int j = 0; j < 4; ++j) {
                phi[j][0] = packh(sacc[2*j][0],   sacc[2*j][1]);
                phi[j][1] = packh(sacc[2*j][2],   sacc[2*j][3]);
                phi[j][2] = packh(sacc[2*j+1][0], sacc[2*j+1][1]);
                phi[j][3] = packh(sacc[2*j+1][2], sacc[2*j+1][3]);
            }

            // ---- O += P V (single fp16 term) ----
            #pragma unroll
            for (int j = 0; j < 4; ++j) {
                #pragma unroll
                for (int pp = 0; pp < 8; ++pp) {
                    const uint32_t off = (uint32_t)((j * 16 + b3 * 8 + w8) * kKVStrideB
                                                    + (pp * 16 + b4 * 8) * 2);
                    uint32_t vh0, vh1, vh2, vh3;
                    ldsm_x4_t(vh0, vh1, vh2, vh3, VHI + off);
                    mma_f16(oacc[2*pp],   phi[j], vh0, vh1);
                    mma_f16(oacc[2*pp+1], phi[j], vh2, vh3);
                }
            }
        }

        // ---- pick up next ticket; prefetch its stage-0 blob before epilogue ----
        __syncthreads();                 // ticket_sm2 visible; stage 0 free (last read iter 30)
        const int next = *ticket_sm2;
        if (next < kTiles) copy_blob(next >> 5, 0, 0);

        // ---- per-tile epilogue (overlaps the prefetch above) ----
        float L0 = l0, L1 = l1;
        #pragma unroll
        for (int off = 1; off <= 2; off <<= 1) {
            L0 += __shfl_xor_sync(0xffffffffu, L0, off);
            L1 += __shfl_xor_sync(0xffffffffu, L1, off);
        }
        const float inv0 = dp / L0, inv1 = dp / L1;
        const size_t row0 = (size_t)bh * kS + (size_t)qt * kBQ + (size_t)(wid * 16 + g);
        float* o0 = out + row0 * kD + 2 * t;
        float* o1 = o0 + (size_t)8 * kD;
        #pragma unroll
        for (int n = 0; n < 16; ++n) {
            *reinterpret_cast<float2*>(o0 + n * 8) = make_float2(oacc[n][0] * inv0, oacc[n][1] * inv0);
            *reinterpret_cast<float2*>(o1 + n * 8) = make_float2(oacc[n][2] * inv1, oacc[n][3] * inv1);
        }

        tile = next;
    }
}

extern "C" void kernel_launch(void* const* d_in, const int* in_sizes, int n_in,
                              void* d_out, int out_size) {
    const float* q  = (const float*)d_in[0];
    const float* k  = (const float*)d_in[1];
    const float* v  = (const float*)d_in[2];
    const float* sf = (const float*)d_in[3];
    const void*  dp = d_in[4];
    float* out = (float*)d_out;
    (void)in_sizes; (void)n_in; (void)out_size;

    dim3 cgrid(kIters, 32);
    convert_kv_kernel<<<cgrid, 256>>>(k, v);   // also resets g_ticket

    cudaFuncSetAttribute(flash_mma_kernel,
                         cudaFuncAttributeMaxDynamicSharedMemorySize, kSmemBytes);
    flash_mma_kernel<<<kPersistentCTAs, kThreads, kSmemBytes>>>(q, sf, dp, out);
}